// round 16
// baseline (speedup 1.0000x reference)
#include <cuda_runtime.h>
#include <cuda_fp16.h>
#include <math.h>
#include <stdint.h>

#define NTOK 4096
#define HD   1024
#define FF   4096
#define NE   8
#define PADM 128
#define MAXR 9216
#define MTILES (MAXR / PADM)      // 72
#define BN   128
#define BK   32
#define SAROW 40                        // smem row stride in halves (80B)
#define STAGE_B (2 * 128 * SAROW * 2)   // A + B per stage = 20480
#define NSTAGES 4
#define SM_TOT (NSTAGES * STAGE_B)      // 81920

// ---------------- scratch ----------------
__device__ __half g_xh[(size_t)MAXR * HD];
__device__ __half g_w1t[(size_t)NE * FF * HD];   // [e][n(FF)][k(HD)]
__device__ __half g_w2t[(size_t)NE * HD * FF];   // [e][n(HD)][k(FF)]
__device__ __half g_h1[(size_t)MAXR * FF];
__device__ __half g_o[(size_t)MAXR * HD];        // fp16 expert outputs
__device__ int    g_tope[NTOK * 2];
__device__ float  g_topw[NTOK * 2];
__device__ int    g_t2r [NTOK * 2];
__device__ int    g_cursor[NE];
__device__ int    g_counts[NE];
__device__ int    g_poff[NE + 1];

// ---------------- PTX helpers ----------------
__device__ __forceinline__ uint32_t smem_u32(const void* p) {
    uint32_t a;
    asm("{ .reg .u64 t; cvta.to.shared.u64 t, %1; cvt.u32.u64 %0, t; }" : "=r"(a) : "l"(p));
    return a;
}
#define CPA16(dst, src) asm volatile("cp.async.cg.shared.global [%0], [%1], 16;" :: "r"(dst), "l"(src))
#define CPA_COMMIT()    asm volatile("cp.async.commit_group;" ::: "memory")
#define CPA_WAIT2()     asm volatile("cp.async.wait_group 2;" ::: "memory")
#define LDSM4(r0, r1, r2, r3, a) \
    asm volatile("ldmatrix.sync.aligned.m8n8.x4.shared.b16 {%0,%1,%2,%3}, [%4];" \
                 : "=r"(r0), "=r"(r1), "=r"(r2), "=r"(r3) : "r"(a))
#define MMA16816(d, a, b) \
    asm volatile("mma.sync.aligned.m16n8k16.row.col.f32.f16.f16.f32 " \
                 "{%0,%1,%2,%3}, {%4,%5,%6,%7}, {%8,%9}, {%0,%1,%2,%3};" \
                 : "+f"((d)[0]), "+f"((d)[1]), "+f"((d)[2]), "+f"((d)[3]) \
                 : "r"((a)[0]), "r"((a)[1]), "r"((a)[2]), "r"((a)[3]), "r"((b)[0]), "r"((b)[1]))

__device__ __forceinline__ float gelu_f(float v) {
    const float c = 0.7978845608028654f;
    float u = c * (v + 0.044715f * v * v * v);
    return 0.5f * v * (1.f + tanhf(u));
}

// ---------------- 1. init ----------------
__global__ void init_kernel() {
    int i = threadIdx.x;
    if (i < NE) { g_counts[i] = 0; g_cursor[i] = 0; }
}

// ---------------- 2. router ----------------
__global__ __launch_bounds__(128) void router_kernel(const float* __restrict__ x,
                                                     const float* __restrict__ Wg,
                                                     float* __restrict__ logits) {
    int t = blockIdx.x;
    const float* xr = x + (size_t)t * HD;
    float acc[NE];
#pragma unroll
    for (int e = 0; e < NE; e++) acc[e] = 0.f;
    for (int j = threadIdx.x; j < HD; j += 128) {
        float xv = xr[j];
        const float4* w4 = reinterpret_cast<const float4*>(Wg + (size_t)j * NE);
        float4 wa = w4[0], wb = w4[1];
        acc[0] += xv * wa.x; acc[1] += xv * wa.y; acc[2] += xv * wa.z; acc[3] += xv * wa.w;
        acc[4] += xv * wb.x; acc[5] += xv * wb.y; acc[6] += xv * wb.z; acc[7] += xv * wb.w;
    }
    __shared__ float s[4][NE];
    int lane = threadIdx.x & 31, warp = threadIdx.x >> 5;
#pragma unroll
    for (int e = 0; e < NE; e++) {
        float v = acc[e];
#pragma unroll
        for (int o = 16; o; o >>= 1) v += __shfl_down_sync(0xffffffffu, v, o);
        if (lane == 0) s[warp][e] = v;
    }
    __syncthreads();
    if (threadIdx.x == 0) {
        float l[NE];
#pragma unroll
        for (int e = 0; e < NE; e++) {
            l[e] = s[0][e] + s[1][e] + s[2][e] + s[3][e];
            logits[(size_t)t * NE + e] = l[e];
        }
        int e0 = 0;
#pragma unroll
        for (int e = 1; e < NE; e++) if (l[e] > l[e0]) e0 = e;
        int e1 = (e0 == 0) ? 1 : 0;
#pragma unroll
        for (int e = 0; e < NE; e++) if (e != e0 && l[e] > l[e1]) e1 = e;
        float w0 = 1.f / (1.f + expf(l[e1] - l[e0]));
        float w1 = 1.f - w0;
        g_tope[t * 2] = e0; g_tope[t * 2 + 1] = e1;
        g_topw[t * 2] = w0; g_topw[t * 2 + 1] = w1;
        atomicAdd(&g_counts[e0], 1);
        atomicAdd(&g_counts[e1], 1);
    }
}

// ---------------- 3. offsets ----------------
__global__ void offsets_kernel() {
    int off = 0;
#pragma unroll
    for (int e = 0; e < NE; e++) {
        g_poff[e] = off;
        off += (g_counts[e] + PADM - 1) / PADM * PADM;
    }
    g_poff[NE] = off;
}

// ---------------- 4. scatter + gather X -> fp16 (fused) ----------------
__global__ __launch_bounds__(128) void scatter_kernel(const float* __restrict__ x) {
    int t = blockIdx.x;
    __shared__ int sr[2];
    if (threadIdx.x == 0) {
#pragma unroll
        for (int k = 0; k < 2; k++) {
            int e = g_tope[t * 2 + k];
            int slot = atomicAdd(&g_cursor[e], 1);
            int r = g_poff[e] + slot;
            g_t2r[t * 2 + k] = r;
            sr[k] = r;
        }
    }
    __syncthreads();
    int r0 = sr[0], r1 = sr[1];
    int c = threadIdx.x * 8;
    float4 v0 = *reinterpret_cast<const float4*>(x + (size_t)t * HD + c);
    float4 v1 = *reinterpret_cast<const float4*>(x + (size_t)t * HD + c + 4);
    __half h[8];
    h[0] = __float2half_rn(v0.x); h[1] = __float2half_rn(v0.y);
    h[2] = __float2half_rn(v0.z); h[3] = __float2half_rn(v0.w);
    h[4] = __float2half_rn(v1.x); h[5] = __float2half_rn(v1.y);
    h[6] = __float2half_rn(v1.z); h[7] = __float2half_rn(v1.w);
    uint4 pk = *reinterpret_cast<uint4*>(h);
    *reinterpret_cast<uint4*>(&g_xh[(size_t)r0 * HD + c]) = pk;
    *reinterpret_cast<uint4*>(&g_xh[(size_t)r1 * HD + c]) = pk;
}

// ---------------- 5. transpose one weight tensor to [e][n][k] fp16 ----------------
__global__ __launch_bounds__(256) void wtrans_kernel(const float* __restrict__ W,
                                                     __half* __restrict__ Wt,
                                                     int K, int N) {
    __shared__ float tile[64][65];
    int tilesN = N >> 6, tilesK = K >> 6;
    int tpe = tilesK * tilesN;
    int e  = blockIdx.x / tpe;
    int rm = blockIdx.x % tpe;
    int kt = rm / tilesN, nt = rm % tilesN;
    int k0 = kt << 6, n0 = nt << 6;
    const float* src = W + (size_t)e * K * N + (size_t)k0 * N + n0;

    int tid = threadIdx.x;
    int tx = tid & 15, ty = tid >> 4;           // 16 x 16
#pragma unroll
    for (int i = 0; i < 4; i++) {
        int k = ty + i * 16;
        float4 v = *reinterpret_cast<const float4*>(src + (size_t)k * N + tx * 4);
        tile[k][tx * 4 + 0] = v.x; tile[k][tx * 4 + 1] = v.y;
        tile[k][tx * 4 + 2] = v.z; tile[k][tx * 4 + 3] = v.w;
    }
    __syncthreads();
    __half* dst = Wt + ((size_t)e * N + n0) * K + k0;
#pragma unroll
    for (int i = 0; i < 4; i++) {
        int n = ty + i * 16;
        __half h[4];
        h[0] = __float2half_rn(tile[tx * 4 + 0][n]);
        h[1] = __float2half_rn(tile[tx * 4 + 1][n]);
        h[2] = __float2half_rn(tile[tx * 4 + 2][n]);
        h[3] = __float2half_rn(tile[tx * 4 + 3][n]);
        *reinterpret_cast<uint2*>(dst + (size_t)n * K + tx * 4) = *reinterpret_cast<uint2*>(h);
    }
}

// ---------------- 6. HMMA grouped GEMM (128x128x32, 4-stage, 2 CTA/SM; fp16 epilogue) ----------------
template <int KTOT, bool GELU>
__global__ __launch_bounds__(256, 2) void mma_gemm_kernel(
    const __half* __restrict__ Amat, const __half* __restrict__ Bmat, int Ndim,
    __half* __restrict__ OutH)
{
    extern __shared__ char smem[];
    uint32_t sb = smem_u32(smem);
    int tid = threadIdx.x;
    int wid = tid >> 5, lane = tid & 31;

    int r0 = blockIdx.x * PADM;
    if (r0 >= g_poff[NE]) return;
    int e = 0;
#pragma unroll
    for (int i = 1; i < NE; i++) if (r0 >= g_poff[i]) e = i;
    int n0 = blockIdx.y * BN;
    const __half* Bp = Bmat + ((size_t)e * Ndim + n0) * KTOT;
    const __half* Ap = Amat + (size_t)r0 * KTOT;

    const int NS = KTOT / BK;
    int wm = wid >> 2, wn = wid & 3;

    float acc[4][4][4];
#pragma unroll
    for (int mi = 0; mi < 4; mi++)
#pragma unroll
        for (int ni = 0; ni < 4; ni++)
#pragma unroll
            for (int q = 0; q < 4; q++) acc[mi][ni][q] = 0.f;

    auto load_stage = [&](int s, int bs) {
#pragma unroll
        for (int it = 0; it < 2; it++) {
            int idx = tid + it * 256;           // 0..511
            int row = idx >> 2, seg = idx & 3;
            uint32_t so = bs * STAGE_B + row * (SAROW * 2) + seg * 16;
            size_t go = (size_t)row * KTOT + s * BK + seg * 8;
            CPA16(sb + so,          Ap + go);
            CPA16(sb + 10240 + so,  Bp + go);
        }
    };

    load_stage(0, 0); CPA_COMMIT();
    load_stage(1, 1); CPA_COMMIT();
    load_stage(2, 2); CPA_COMMIT();

    int lr = lane & 15, lc = lane >> 4;
    for (int s = 0; s < NS; s++) {
        CPA_WAIT2();
        __syncthreads();
        if (s + 3 < NS) load_stage(s + 3, (s + 3) % NSTAGES);
        CPA_COMMIT();

        uint32_t aB = sb + (s % NSTAGES) * STAGE_B;
        uint32_t bB = aB + 10240;
#pragma unroll
        for (int ks = 0; ks < 2; ks++) {
            uint32_t ah[4][4], bf[4][2];
#pragma unroll
            for (int bi = 0; bi < 2; bi++) {
                uint32_t t0, t1, t2, t3;
                uint32_t addr = bB + (wn * 32 + bi * 16 + lr) * (SAROW * 2) + ks * 32 + lc * 16;
                LDSM4(t0, t1, t2, t3, addr);
                bf[bi * 2 + 0][0] = t0; bf[bi * 2 + 0][1] = t2;
                bf[bi * 2 + 1][0] = t1; bf[bi * 2 + 1][1] = t3;
            }
#pragma unroll
            for (int mi = 0; mi < 4; mi++) {
                uint32_t addr = aB + (wm * 64 + mi * 16 + lr) * (SAROW * 2) + ks * 32 + lc * 16;
                LDSM4(ah[mi][0], ah[mi][1], ah[mi][2], ah[mi][3], addr);
            }
#pragma unroll
            for (int mi = 0; mi < 4; mi++)
#pragma unroll
                for (int ni = 0; ni < 4; ni++)
                    MMA16816(acc[mi][ni], ah[mi], bf[ni]);
        }
        __syncthreads();
    }

    int rbase = r0 + wm * 64 + (lane >> 2);
    int cbase = n0 + wn * 32 + (lane & 3) * 2;
    int ostride = GELU ? FF : HD;
#pragma unroll
    for (int mi = 0; mi < 4; mi++) {
#pragma unroll
        for (int ni = 0; ni < 4; ni++) {
#pragma unroll
            for (int half = 0; half < 2; half++) {
                int r = rbase + mi * 16 + half * 8;
                int c = cbase + ni * 8;
                float v0 = acc[mi][ni][half * 2 + 0];
                float v1 = acc[mi][ni][half * 2 + 1];
                if (GELU) { v0 = gelu_f(v0); v1 = gelu_f(v1); }
                __half2 hh = __halves2half2(__float2half_rn(v0), __float2half_rn(v1));
                *reinterpret_cast<__half2*>(&OutH[(size_t)r * ostride + c]) = hh;
            }
        }
    }
}

// ---------------- 7. combine (fp16 inputs, fp32 math/output) ----------------
__global__ __launch_bounds__(128) void combine_kernel(float* __restrict__ out) {
    int t = blockIdx.x;
    int r0 = g_t2r[t * 2], r1 = g_t2r[t * 2 + 1];
    float w0 = g_topw[t * 2], w1 = g_topw[t * 2 + 1];
    int c = threadIdx.x * 8;
    uint4 pa = *reinterpret_cast<const uint4*>(g_o + (size_t)r0 * HD + c);
    uint4 pb = *reinterpret_cast<const uint4*>(g_o + (size_t)r1 * HD + c);
    const __half2* ha = reinterpret_cast<const __half2*>(&pa);
    const __half2* hb = reinterpret_cast<const __half2*>(&pb);
    float o[8];
#pragma unroll
    for (int q = 0; q < 4; q++) {
        float2 a = __half22float2(ha[q]);
        float2 b = __half22float2(hb[q]);
        o[q * 2 + 0] = w0 * a.x + w1 * b.x;
        o[q * 2 + 1] = w0 * a.y + w1 * b.y;
    }
    float4 o01 = make_float4(o[0], o[1], o[2], o[3]);
    float4 o23 = make_float4(o[4], o[5], o[6], o[7]);
    *reinterpret_cast<float4*>(out + (size_t)t * HD + c)     = o01;
    *reinterpret_cast<float4*>(out + (size_t)t * HD + c + 4) = o23;
}

// ---------------- 8. aux loss ----------------
__global__ __launch_bounds__(256) void aux_kernel(const float* __restrict__ logits,
                                                  float* __restrict__ aux_out) {
    __shared__ float red[256][17];
    float acc[NE], freq[NE];
#pragma unroll
    for (int e = 0; e < NE; e++) { acc[e] = 0.f; freq[e] = 0.f; }
    float z = 0.f;
    for (int t = threadIdx.x; t < NTOK; t += 256) {
        float l[NE];
#pragma unroll
        for (int e = 0; e < NE; e++) l[e] = logits[(size_t)t * NE + e];
        float m = l[0];
#pragma unroll
        for (int e = 1; e < NE; e++) m = fmaxf(m, l[e]);
        float p[NE], s = 0.f;
#pragma unroll
        for (int e = 0; e < NE; e++) { p[e] = expf(l[e] - m); s += p[e]; }
        float inv = 1.f / s;
#pragma unroll
        for (int e = 0; e < NE; e++) acc[e] += p[e] * inv;
        float lse = m + logf(s);
        z += lse * lse;
        int e0 = 0;
#pragma unroll
        for (int e = 1; e < NE; e++) if (l[e] > l[e0]) e0 = e;
        int e1 = (e0 == 0) ? 1 : 0;
#pragma unroll
        for (int e = 0; e < NE; e++) if (e != e0 && l[e] > l[e1]) e1 = e;
        freq[e0] += 1.f; freq[e1] += 1.f;
    }
    int tid = threadIdx.x;
#pragma unroll
    for (int e = 0; e < NE; e++) { red[tid][e] = acc[e]; red[tid][8 + e] = freq[e]; }
    red[tid][16] = z;
    __syncthreads();
    for (int s2 = 128; s2; s2 >>= 1) {
        if (tid < s2)
#pragma unroll
            for (int c = 0; c < 17; c++) red[tid][c] += red[tid + s2][c];
        __syncthreads();
    }
    if (tid == 0) {
        float sp = 0.f, sf = 0.f;
#pragma unroll
        for (int e = 0; e < NE; e++) { sp += red[0][e]; sf += red[0][8 + e]; }
        float sw = 0.f;
#pragma unroll
        for (int e = 0; e < NE; e++) sw += (red[0][e] / sp) * (red[0][8 + e] / sf);
        sw *= (float)NE;
        float zl = red[0][16] / (float)NTOK;
        aux_out[0] = sw + 0.1f * zl;
    }
}

// ---------------- entry ----------------
extern "C" void kernel_launch(void* const* d_in, const int* in_sizes, int n_in,
                              void* d_out, int out_size) {
    const float* x  = (const float*)d_in[0];
    const float* Wg = (const float*)d_in[1];
    const float* W1 = (const float*)d_in[2];
    const float* W2 = (const float*)d_in[3];
    float* out    = (float*)d_out;
    float* logits = out + (size_t)NTOK * HD;
    float* aux    = logits + (size_t)NTOK * NE;

    cudaFuncSetAttribute(mma_gemm_kernel<HD, true>,
                         cudaFuncAttributeMaxDynamicSharedMemorySize, SM_TOT);
    cudaFuncSetAttribute(mma_gemm_kernel<FF, false>,
                         cudaFuncAttributeMaxDynamicSharedMemorySize, SM_TOT);

    __half *xh, *w1t, *w2t, *h1, *o_ptr;
    cudaGetSymbolAddress((void**)&xh,  g_xh);
    cudaGetSymbolAddress((void**)&w1t, g_w1t);
    cudaGetSymbolAddress((void**)&w2t, g_w2t);
    cudaGetSymbolAddress((void**)&h1,  g_h1);
    cudaGetSymbolAddress((void**)&o_ptr, g_o);

    // one-time host-side stream/event creation (no device memory involved)
    static cudaStream_t s_side = nullptr;
    static cudaEvent_t evFork = nullptr, evW1 = nullptr, evW2 = nullptr;
    static cudaEvent_t evLog = nullptr, evAux = nullptr;
    if (s_side == nullptr) {
        cudaStreamCreateWithFlags(&s_side, cudaStreamNonBlocking);
        cudaEventCreateWithFlags(&evFork, cudaEventDisableTiming);
        cudaEventCreateWithFlags(&evW1,   cudaEventDisableTiming);
        cudaEventCreateWithFlags(&evW2,   cudaEventDisableTiming);
        cudaEventCreateWithFlags(&evLog,  cudaEventDisableTiming);
        cudaEventCreateWithFlags(&evAux,  cudaEventDisableTiming);
    }

    // fork: side stream does weight transposes while main stream routes/scatters
    cudaEventRecord(evFork, 0);
    cudaStreamWaitEvent(s_side, evFork, 0);
    wtrans_kernel<<<NE * (HD / 64) * (FF / 64), 256, 0, s_side>>>(W1, w1t, HD, FF);
    cudaEventRecord(evW1, s_side);
    wtrans_kernel<<<NE * (FF / 64) * (HD / 64), 256, 0, s_side>>>(W2, w2t, FF, HD);
    cudaEventRecord(evW2, s_side);

    // main stream: routing pipeline
    init_kernel<<<1, 32>>>();
    router_kernel<<<NTOK, 128>>>(x, Wg, logits);
    cudaEventRecord(evLog, 0);                 // logits ready
    offsets_kernel<<<1, 1>>>();
    scatter_kernel<<<NTOK, 128>>>(x);

    // aux loss on side stream (hides under GEMM1)
    cudaStreamWaitEvent(s_side, evLog, 0);
    aux_kernel<<<1, 256, 0, s_side>>>(logits, aux);
    cudaEventRecord(evAux, s_side);

    // join W1t, run GEMM1 (W2t still converting underneath)
    cudaStreamWaitEvent(0, evW1, 0);
    mma_gemm_kernel<HD, true><<<dim3(MTILES, FF / BN), 256, SM_TOT>>>(xh, w1t, FF, h1);
    // join W2t, run GEMM2 (fp16 output to g_o)
    cudaStreamWaitEvent(0, evW2, 0);
    mma_gemm_kernel<FF, false><<<dim3(MTILES, HD / BN), 256, SM_TOT>>>(h1, w2t, HD, o_ptr);

    combine_kernel<<<NTOK, 128>>>(out);
    cudaStreamWaitEvent(0, evAux, 0);          // aux must complete before stream end
}

// round 17
// speedup vs baseline: 1.0306x; 1.0306x over previous
#include <cuda_runtime.h>
#include <cuda_fp16.h>
#include <math.h>
#include <stdint.h>

#define NTOK 4096
#define HD   1024
#define FF   4096
#define NE   8
#define PADM 128
#define MAXR 9216
#define MTILES (MAXR / PADM)      // 72
#define BN   128
#define BK   32
#define SAROW 40                        // smem row stride in halves (80B)
#define STAGE_B (2 * 128 * SAROW * 2)   // A + B per stage = 20480
#define NSTAGES 4
#define SM_TOT (NSTAGES * STAGE_B)      // 81920

// ---------------- scratch ----------------
__device__ __half g_xh[(size_t)NTOK * HD];       // token-ordered fp16 x
__device__ __half g_w1t[(size_t)NE * FF * HD];   // [e][n(FF)][k(HD)]
__device__ __half g_w2t[(size_t)NE * HD * FF];   // [e][n(HD)][k(FF)]
__device__ __half g_h1[(size_t)MAXR * FF];
__device__ __half g_o[(size_t)MAXR * HD];        // fp16 expert outputs
__device__ int    g_tope[NTOK * 2];
__device__ float  g_topw[NTOK * 2];
__device__ int    g_rows[MAXR];                  // grouped row -> token (pad stays 0)
__device__ int    g_t2r [NTOK * 2];
__device__ int    g_cursor[NE];
__device__ int    g_counts[NE];
__device__ int    g_poff[NE + 1];

// ---------------- PTX helpers ----------------
__device__ __forceinline__ uint32_t smem_u32(const void* p) {
    uint32_t a;
    asm("{ .reg .u64 t; cvta.to.shared.u64 t, %1; cvt.u32.u64 %0, t; }" : "=r"(a) : "l"(p));
    return a;
}
#define CPA16(dst, src) asm volatile("cp.async.cg.shared.global [%0], [%1], 16;" :: "r"(dst), "l"(src))
#define CPA_COMMIT()    asm volatile("cp.async.commit_group;" ::: "memory")
#define CPA_WAIT2()     asm volatile("cp.async.wait_group 2;" ::: "memory")
#define LDSM4(r0, r1, r2, r3, a) \
    asm volatile("ldmatrix.sync.aligned.m8n8.x4.shared.b16 {%0,%1,%2,%3}, [%4];" \
                 : "=r"(r0), "=r"(r1), "=r"(r2), "=r"(r3) : "r"(a))
#define MMA16816(d, a, b) \
    asm volatile("mma.sync.aligned.m16n8k16.row.col.f32.f16.f16.f32 " \
                 "{%0,%1,%2,%3}, {%4,%5,%6,%7}, {%8,%9}, {%0,%1,%2,%3};" \
                 : "+f"((d)[0]), "+f"((d)[1]), "+f"((d)[2]), "+f"((d)[3]) \
                 : "r"((a)[0]), "r"((a)[1]), "r"((a)[2]), "r"((a)[3]), "r"((b)[0]), "r"((b)[1]))

__device__ __forceinline__ float gelu_f(float v) {
    const float c = 0.7978845608028654f;
    float u = c * (v + 0.044715f * v * v * v);
    return 0.5f * v * (1.f + tanhf(u));
}

// ---------------- router ----------------
__global__ __launch_bounds__(128) void router_kernel(const float* __restrict__ x,
                                                     const float* __restrict__ Wg,
                                                     float* __restrict__ logits) {
    int t = blockIdx.x;
    const float* xr = x + (size_t)t * HD;
    float acc[NE];
#pragma unroll
    for (int e = 0; e < NE; e++) acc[e] = 0.f;
    for (int j = threadIdx.x; j < HD; j += 128) {
        float xv = xr[j];
        const float4* w4 = reinterpret_cast<const float4*>(Wg + (size_t)j * NE);
        float4 wa = w4[0], wb = w4[1];
        acc[0] += xv * wa.x; acc[1] += xv * wa.y; acc[2] += xv * wa.z; acc[3] += xv * wa.w;
        acc[4] += xv * wb.x; acc[5] += xv * wb.y; acc[6] += xv * wb.z; acc[7] += xv * wb.w;
    }
    __shared__ float s[4][NE];
    int lane = threadIdx.x & 31, warp = threadIdx.x >> 5;
#pragma unroll
    for (int e = 0; e < NE; e++) {
        float v = acc[e];
#pragma unroll
        for (int o = 16; o; o >>= 1) v += __shfl_down_sync(0xffffffffu, v, o);
        if (lane == 0) s[warp][e] = v;
    }
    __syncthreads();
    if (threadIdx.x == 0) {
        float l[NE];
#pragma unroll
        for (int e = 0; e < NE; e++) {
            l[e] = s[0][e] + s[1][e] + s[2][e] + s[3][e];
            logits[(size_t)t * NE + e] = l[e];
        }
        int e0 = 0;
#pragma unroll
        for (int e = 1; e < NE; e++) if (l[e] > l[e0]) e0 = e;
        int e1 = (e0 == 0) ? 1 : 0;
#pragma unroll
        for (int e = 0; e < NE; e++) if (e != e0 && l[e] > l[e1]) e1 = e;
        float w0 = 1.f / (1.f + expf(l[e1] - l[e0]));
        float w1 = 1.f - w0;
        g_tope[t * 2] = e0; g_tope[t * 2 + 1] = e1;
        g_topw[t * 2] = w0; g_topw[t * 2 + 1] = w1;
        atomicAdd(&g_counts[e0], 1);
        atomicAdd(&g_counts[e1], 1);
    }
}

// ---------------- offsets ----------------
__global__ void offsets_kernel() {
    int off = 0;
#pragma unroll
    for (int e = 0; e < NE; e++) {
        g_poff[e] = off;
        off += (g_counts[e] + PADM - 1) / PADM * PADM;
    }
    g_poff[NE] = off;
}

// ---------------- scatter (slot assignment only) ----------------
__global__ void scatter_kernel() {
    int t = blockIdx.x * blockDim.x + threadIdx.x;
    if (t >= NTOK) return;
#pragma unroll
    for (int k = 0; k < 2; k++) {
        int e = g_tope[t * 2 + k];
        int slot = atomicAdd(&g_cursor[e], 1);
        int r = g_poff[e] + slot;
        g_rows[r] = t;
        g_t2r[t * 2 + k] = r;
    }
}

// ---------------- xconv: token-ordered fp32 -> fp16 (no routing dependency) ----------------
__global__ __launch_bounds__(256) void xconv_kernel(const float* __restrict__ x) {
    size_t i = ((size_t)blockIdx.x * 256 + threadIdx.x) * 8;   // grid 2048 covers NTOK*HD
    float4 v0 = *reinterpret_cast<const float4*>(x + i);
    float4 v1 = *reinterpret_cast<const float4*>(x + i + 4);
    __half h[8];
    h[0] = __float2half_rn(v0.x); h[1] = __float2half_rn(v0.y);
    h[2] = __float2half_rn(v0.z); h[3] = __float2half_rn(v0.w);
    h[4] = __float2half_rn(v1.x); h[5] = __float2half_rn(v1.y);
    h[6] = __float2half_rn(v1.z); h[7] = __float2half_rn(v1.w);
    *reinterpret_cast<uint4*>(&g_xh[i]) = *reinterpret_cast<uint4*>(h);
}

// ---------------- weight transpose (n-tile windowed) ----------------
__global__ __launch_bounds__(256) void wtrans_kernel(const float* __restrict__ W,
                                                     __half* __restrict__ Wt,
                                                     int K, int N, int ntBase, int ntCnt) {
    __shared__ float tile[64][65];
    int tilesK = K >> 6;
    int tpe = tilesK * ntCnt;
    int e  = blockIdx.x / tpe;
    int rm = blockIdx.x % tpe;
    int kt = rm / ntCnt, nt = ntBase + rm % ntCnt;
    int k0 = kt << 6, n0 = nt << 6;
    const float* src = W + (size_t)e * K * N + (size_t)k0 * N + n0;

    int tid = threadIdx.x;
    int tx = tid & 15, ty = tid >> 4;           // 16 x 16
#pragma unroll
    for (int i = 0; i < 4; i++) {
        int k = ty + i * 16;
        float4 v = *reinterpret_cast<const float4*>(src + (size_t)k * N + tx * 4);
        tile[k][tx * 4 + 0] = v.x; tile[k][tx * 4 + 1] = v.y;
        tile[k][tx * 4 + 2] = v.z; tile[k][tx * 4 + 3] = v.w;
    }
    __syncthreads();
    __half* dst = Wt + ((size_t)e * N + n0) * K + k0;
#pragma unroll
    for (int i = 0; i < 4; i++) {
        int n = ty + i * 16;
        __half h[4];
        h[0] = __float2half_rn(tile[tx * 4 + 0][n]);
        h[1] = __float2half_rn(tile[tx * 4 + 1][n]);
        h[2] = __float2half_rn(tile[tx * 4 + 2][n]);
        h[3] = __float2half_rn(tile[tx * 4 + 3][n]);
        *reinterpret_cast<uint2*>(dst + (size_t)n * K + tx * 4) = *reinterpret_cast<uint2*>(h);
    }
}

// ---------------- HMMA grouped GEMM (R4 config; optional A row-gather) ----------------
template <int KTOT, bool GELU, bool GATHER>
__global__ __launch_bounds__(256, 2) void mma_gemm_kernel(
    const __half* __restrict__ Amat, const __half* __restrict__ Bmat, int Ndim,
    __half* __restrict__ OutH, int yBase)
{
    extern __shared__ char smem[];
    __shared__ int stok[PADM];
    uint32_t sb = smem_u32(smem);
    int tid = threadIdx.x;
    int wid = tid >> 5, lane = tid & 31;

    int r0 = blockIdx.x * PADM;
    if (r0 >= g_poff[NE]) return;
    int e = 0;
#pragma unroll
    for (int i = 1; i < NE; i++) if (r0 >= g_poff[i]) e = i;
    int n0 = (blockIdx.y + yBase) * BN;
    const __half* Bp = Bmat + ((size_t)e * Ndim + n0) * KTOT;

    if (GATHER) {
        if (tid < PADM) stok[tid] = g_rows[r0 + tid];
        __syncthreads();
    }

    const int NS = KTOT / BK;
    int wm = wid >> 2, wn = wid & 3;

    float acc[4][4][4];
#pragma unroll
    for (int mi = 0; mi < 4; mi++)
#pragma unroll
        for (int ni = 0; ni < 4; ni++)
#pragma unroll
            for (int q = 0; q < 4; q++) acc[mi][ni][q] = 0.f;

    auto load_stage = [&](int s, int bs) {
#pragma unroll
        for (int it = 0; it < 2; it++) {
            int idx = tid + it * 256;           // 0..511
            int row = idx >> 2, seg = idx & 3;
            uint32_t so = bs * STAGE_B + row * (SAROW * 2) + seg * 16;
            size_t arow = GATHER ? (size_t)stok[row] * KTOT : (size_t)(r0 + row) * KTOT;
            CPA16(sb + so,          Amat + arow + s * BK + seg * 8);
            CPA16(sb + 10240 + so,  Bp + (size_t)row * KTOT + s * BK + seg * 8);
        }
    };

    load_stage(0, 0); CPA_COMMIT();
    load_stage(1, 1); CPA_COMMIT();
    load_stage(2, 2); CPA_COMMIT();

    int lr = lane & 15, lc = lane >> 4;
    for (int s = 0; s < NS; s++) {
        CPA_WAIT2();
        __syncthreads();
        if (s + 3 < NS) load_stage(s + 3, (s + 3) % NSTAGES);
        CPA_COMMIT();

        uint32_t aB = sb + (s % NSTAGES) * STAGE_B;
        uint32_t bB = aB + 10240;
#pragma unroll
        for (int ks = 0; ks < 2; ks++) {
            uint32_t ah[4][4], bf[4][2];
#pragma unroll
            for (int bi = 0; bi < 2; bi++) {
                uint32_t t0, t1, t2, t3;
                uint32_t addr = bB + (wn * 32 + bi * 16 + lr) * (SAROW * 2) + ks * 32 + lc * 16;
                LDSM4(t0, t1, t2, t3, addr);
                bf[bi * 2 + 0][0] = t0; bf[bi * 2 + 0][1] = t2;
                bf[bi * 2 + 1][0] = t1; bf[bi * 2 + 1][1] = t3;
            }
#pragma unroll
            for (int mi = 0; mi < 4; mi++) {
                uint32_t addr = aB + (wm * 64 + mi * 16 + lr) * (SAROW * 2) + ks * 32 + lc * 16;
                LDSM4(ah[mi][0], ah[mi][1], ah[mi][2], ah[mi][3], addr);
            }
#pragma unroll
            for (int mi = 0; mi < 4; mi++)
#pragma unroll
                for (int ni = 0; ni < 4; ni++)
                    MMA16816(acc[mi][ni], ah[mi], bf[ni]);
        }
        __syncthreads();
    }

    int rbase = r0 + wm * 64 + (lane >> 2);
    int cbase = n0 + wn * 32 + (lane & 3) * 2;
    int ostride = GELU ? FF : HD;
#pragma unroll
    for (int mi = 0; mi < 4; mi++) {
#pragma unroll
        for (int ni = 0; ni < 4; ni++) {
#pragma unroll
            for (int half = 0; half < 2; half++) {
                int r = rbase + mi * 16 + half * 8;
                int c = cbase + ni * 8;
                float v0 = acc[mi][ni][half * 2 + 0];
                float v1 = acc[mi][ni][half * 2 + 1];
                if (GELU) { v0 = gelu_f(v0); v1 = gelu_f(v1); }
                __half2 hh = __halves2half2(__float2half_rn(v0), __float2half_rn(v1));
                *reinterpret_cast<__half2*>(&OutH[(size_t)r * ostride + c]) = hh;
            }
        }
    }
}

// ---------------- combine (fp16 inputs, fp32 output; resets counters for next replay) ----------------
__global__ __launch_bounds__(128) void combine_kernel(float* __restrict__ out) {
    int t = blockIdx.x;
    if (t == 0 && threadIdx.x < NE) { g_counts[threadIdx.x] = 0; g_cursor[threadIdx.x] = 0; }
    int r0 = g_t2r[t * 2], r1 = g_t2r[t * 2 + 1];
    float w0 = g_topw[t * 2], w1 = g_topw[t * 2 + 1];
    int c = threadIdx.x * 8;
    uint4 pa = *reinterpret_cast<const uint4*>(g_o + (size_t)r0 * HD + c);
    uint4 pb = *reinterpret_cast<const uint4*>(g_o + (size_t)r1 * HD + c);
    const __half2* ha = reinterpret_cast<const __half2*>(&pa);
    const __half2* hb = reinterpret_cast<const __half2*>(&pb);
    float o[8];
#pragma unroll
    for (int q = 0; q < 4; q++) {
        float2 a = __half22float2(ha[q]);
        float2 b = __half22float2(hb[q]);
        o[q * 2 + 0] = w0 * a.x + w1 * b.x;
        o[q * 2 + 1] = w0 * a.y + w1 * b.y;
    }
    float4 o01 = make_float4(o[0], o[1], o[2], o[3]);
    float4 o23 = make_float4(o[4], o[5], o[6], o[7]);
    *reinterpret_cast<float4*>(out + (size_t)t * HD + c)     = o01;
    *reinterpret_cast<float4*>(out + (size_t)t * HD + c + 4) = o23;
}

// ---------------- aux loss ----------------
__global__ __launch_bounds__(256) void aux_kernel(const float* __restrict__ logits,
                                                  float* __restrict__ aux_out) {
    __shared__ float red[256][17];
    float acc[NE], freq[NE];
#pragma unroll
    for (int e = 0; e < NE; e++) { acc[e] = 0.f; freq[e] = 0.f; }
    float z = 0.f;
    for (int t = threadIdx.x; t < NTOK; t += 256) {
        float l[NE];
#pragma unroll
        for (int e = 0; e < NE; e++) l[e] = logits[(size_t)t * NE + e];
        float m = l[0];
#pragma unroll
        for (int e = 1; e < NE; e++) m = fmaxf(m, l[e]);
        float p[NE], s = 0.f;
#pragma unroll
        for (int e = 0; e < NE; e++) { p[e] = expf(l[e] - m); s += p[e]; }
        float inv = 1.f / s;
#pragma unroll
        for (int e = 0; e < NE; e++) acc[e] += p[e] * inv;
        float lse = m + logf(s);
        z += lse * lse;
        int e0 = 0;
#pragma unroll
        for (int e = 1; e < NE; e++) if (l[e] > l[e0]) e0 = e;
        int e1 = (e0 == 0) ? 1 : 0;
#pragma unroll
        for (int e = 0; e < NE; e++) if (e != e0 && l[e] > l[e1]) e1 = e;
        freq[e0] += 1.f; freq[e1] += 1.f;
    }
    int tid = threadIdx.x;
#pragma unroll
    for (int e = 0; e < NE; e++) { red[tid][e] = acc[e]; red[tid][8 + e] = freq[e]; }
    red[tid][16] = z;
    __syncthreads();
    for (int s2 = 128; s2; s2 >>= 1) {
        if (tid < s2)
#pragma unroll
            for (int c = 0; c < 17; c++) red[tid][c] += red[tid + s2][c];
        __syncthreads();
    }
    if (tid == 0) {
        float sp = 0.f, sf = 0.f;
#pragma unroll
        for (int e = 0; e < NE; e++) { sp += red[0][e]; sf += red[0][8 + e]; }
        float sw = 0.f;
#pragma unroll
        for (int e = 0; e < NE; e++) sw += (red[0][e] / sp) * (red[0][8 + e] / sf);
        sw *= (float)NE;
        float zl = red[0][16] / (float)NTOK;
        aux_out[0] = sw + 0.1f * zl;
    }
}

// ---------------- entry ----------------
extern "C" void kernel_launch(void* const* d_in, const int* in_sizes, int n_in,
                              void* d_out, int out_size) {
    const float* x  = (const float*)d_in[0];
    const float* Wg = (const float*)d_in[1];
    const float* W1 = (const float*)d_in[2];
    const float* W2 = (const float*)d_in[3];
    float* out    = (float*)d_out;
    float* logits = out + (size_t)NTOK * HD;
    float* aux    = logits + (size_t)NTOK * NE;

    cudaFuncSetAttribute(mma_gemm_kernel<HD, true, true>,
                         cudaFuncAttributeMaxDynamicSharedMemorySize, SM_TOT);
    cudaFuncSetAttribute(mma_gemm_kernel<FF, false, false>,
                         cudaFuncAttributeMaxDynamicSharedMemorySize, SM_TOT);

    __half *xh, *w1t, *w2t, *h1, *o_ptr;
    cudaGetSymbolAddress((void**)&xh,  g_xh);
    cudaGetSymbolAddress((void**)&w1t, g_w1t);
    cudaGetSymbolAddress((void**)&w2t, g_w2t);
    cudaGetSymbolAddress((void**)&h1,  g_h1);
    cudaGetSymbolAddress((void**)&o_ptr, g_o);

    static cudaStream_t sA = nullptr, sB = nullptr;
    static cudaEvent_t evFork = nullptr, evW1A = nullptr, evXC = nullptr, evW2 = nullptr;
    static cudaEvent_t evLog = nullptr, evScat = nullptr, evG1B = nullptr, evAux = nullptr;
    if (sA == nullptr) {
        cudaStreamCreateWithFlags(&sA, cudaStreamNonBlocking);
        cudaStreamCreateWithFlags(&sB, cudaStreamNonBlocking);
        cudaEventCreateWithFlags(&evFork, cudaEventDisableTiming);
        cudaEventCreateWithFlags(&evW1A,  cudaEventDisableTiming);
        cudaEventCreateWithFlags(&evXC,   cudaEventDisableTiming);
        cudaEventCreateWithFlags(&evW2,   cudaEventDisableTiming);
        cudaEventCreateWithFlags(&evLog,  cudaEventDisableTiming);
        cudaEventCreateWithFlags(&evScat, cudaEventDisableTiming);
        cudaEventCreateWithFlags(&evG1B,  cudaEventDisableTiming);
        cudaEventCreateWithFlags(&evAux,  cudaEventDisableTiming);
    }

    cudaEventRecord(evFork, 0);
    cudaStreamWaitEvent(sA, evFork, 0);
    cudaStreamWaitEvent(sB, evFork, 0);

    // stream A: W1 transpose halves, then GEMM1_B (y-blocks 16..31)
    wtrans_kernel<<<NE * (HD / 64) * 32, 256, 0, sA>>>(W1, w1t, HD, FF, 0, 32);
    cudaEventRecord(evW1A, sA);
    wtrans_kernel<<<NE * (HD / 64) * 32, 256, 0, sA>>>(W1, w1t, HD, FF, 32, 32);

    // stream B: xconv, W2 transpose, aux
    xconv_kernel<<<(NTOK * HD) / (256 * 8), 256, 0, sB>>>(x);
    cudaEventRecord(evXC, sB);
    wtrans_kernel<<<NE * (FF / 64) * 16, 256, 0, sB>>>(W2, w2t, FF, HD, 0, 16);
    cudaEventRecord(evW2, sB);

    // main: routing chain
    router_kernel<<<NTOK, 128>>>(x, Wg, logits);
    cudaEventRecord(evLog, 0);
    offsets_kernel<<<1, 1>>>();
    scatter_kernel<<<(NTOK + 255) / 256, 256>>>();
    cudaEventRecord(evScat, 0);

    // aux on stream B (after logits; hides under GEMM1)
    cudaStreamWaitEvent(sB, evLog, 0);
    aux_kernel<<<1, 256, 0, sB>>>(logits, aux);
    cudaEventRecord(evAux, sB);

    // GEMM1_A on main (y 0..15): needs scatter (in-stream), xconv, W1t first half
    cudaStreamWaitEvent(0, evXC, 0);
    cudaStreamWaitEvent(0, evW1A, 0);
    mma_gemm_kernel<HD, true, true><<<dim3(MTILES, 16), 256, SM_TOT>>>(xh, w1t, FF, h1, 0);

    // GEMM1_B on stream A (y 16..31): after W1tB (in-stream) + scatter + xconv
    cudaStreamWaitEvent(sA, evScat, 0);
    cudaStreamWaitEvent(sA, evXC, 0);
    mma_gemm_kernel<HD, true, true><<<dim3(MTILES, 16), 256, SM_TOT, sA>>>(xh, w1t, FF, h1, 16);
    cudaEventRecord(evG1B, sA);

    // GEMM2 on main: after GEMM1_A (in-stream) + GEMM1_B + W2t
    cudaStreamWaitEvent(0, evG1B, 0);
    cudaStreamWaitEvent(0, evW2, 0);
    mma_gemm_kernel<FF, false, false><<<dim3(MTILES, HD / BN), 256, SM_TOT>>>(h1, w2t, HD, o_ptr, 0);

    combine_kernel<<<NTOK, 128>>>(out);
    cudaStreamWaitEvent(0, evAux, 0);          // aux must complete before stream end
}